// round 14
// baseline (speedup 1.0000x reference)
#include <cuda_runtime.h>
#include <math.h>
#include <stdint.h>

// ---------------- problem constants ----------------
#define NLITS 4000
#define NCLS  8000
#define E     128
#define H1    400
#define H2    200
#define H2P   208          // H2 padded to multiple of 16
#define NG    512          // 4*E LSTM gates
#define TSTEPS 30
#define LIT_STRIDE 512
#define CLS_STRIDE 256
#define VOTE_BLOCKS ((NLITS + 7) / 8)

// GEMM tiling: block tile 128(M) x 64(N), 8 warps (4 over M x 2 over N)
#define BK 16
#define SPB 80                  // smem row stride bytes (16 floats + 4 pad)
#define TILEB_A (128 * SPB)     // 10240 B
#define TILEB_B (64 * SPB)      // 5120 B
#define STAGE_BYTES (TILEB_A + 2 * TILEB_B)   // A, Bh, Bl = 20480 B
#define STAGES 3
#define GEMM_SMEM (STAGES * STAGE_BYTES)      // 61440 B; 3 blocks/SM

// ---------------- device scratch (static, BSS zero-init, allocation-free) ----------------
__device__ float g_LhA[NLITS * E], g_LhB[NLITS * E], g_Lc[NLITS * E];
__device__ float g_ChA[NCLS * E],  g_ChB[NCLS * E],  g_Cc[NCLS * E];
__device__ float g_b1L[NLITS * H1], g_b1C[NCLS * H1];
__device__ float g_b2L[NLITS * H2P], g_b2C[NCLS * H2P];   // pad cols [200,208) stay 0
__device__ float g_mlpL[NLITS * E],  g_mlpC[NCLS * E];
__device__ float g_msgL[NLITS * E],  g_msgC[NCLS * E];

// pre-split weights (tf32-valued fp32 hi/lo), K padded where needed
__device__ float g_LC1h[H1 * E],   g_LC1l[H1 * E];
__device__ float g_LC2h[H2 * H1],  g_LC2l[H2 * H1];
__device__ float g_LC3h[E * H2P],  g_LC3l[E * H2P];
__device__ float g_CL1h[H1 * E],   g_CL1l[H1 * E];
__device__ float g_CL2h[H2 * H1],  g_CL2l[H2 * H1];
__device__ float g_CL3h[E * H2P],  g_CL3l[E * H2P];
__device__ float g_CWih[NG * E],   g_CWil[NG * E];   // gate-interleaved rows
__device__ float g_CWhh[NG * E],   g_CWhl[NG * E];
__device__ float g_LWih[NG * E],   g_LWil[NG * E];
__device__ float g_LWhh[NG * E],   g_LWhl[NG * E];
__device__ float g_VW1h[H1 * E],   g_VW1l[H1 * E];
__device__ float g_VW2h[H2 * H1],  g_VW2l[H2 * H1];

__device__ int   g_lit_idx[(size_t)NLITS * LIT_STRIDE];
__device__ int   g_lit_len[NLITS];
__device__ int   g_cls_idx[(size_t)NCLS * CLS_STRIDE];
__device__ int   g_cls_len[NCLS];
__device__ float g_partials[VOTE_BLOCKS];

// ---------------- helpers ----------------
__device__ __forceinline__ unsigned smem_u32(const void* p) {
    return (unsigned)__cvta_generic_to_shared(p);
}
__device__ __forceinline__ void tf32_split(float v, uint32_t& h, uint32_t& l) {
    asm("cvt.rna.tf32.f32 %0, %1;" : "=r"(h) : "f"(v));
    float r = v - __uint_as_float(h);
    asm("cvt.rna.tf32.f32 %0, %1;" : "=r"(l) : "f"(r));
}
__device__ __forceinline__ void cp16(uint32_t dst, const void* src, bool valid) {
    int sz = valid ? 16 : 0;
    asm volatile("cp.async.cg.shared.global [%0], [%1], 16, %2;"
                 :: "r"(dst), "l"(src), "r"(sz) : "memory");
}
#define CP_COMMIT() asm volatile("cp.async.commit_group;" ::: "memory")
#define CP_WAIT1()  asm volatile("cp.async.wait_group 1;" ::: "memory")
#define CP_WAIT0()  asm volatile("cp.async.wait_group 0;" ::: "memory")

#define LDSM4(R0, R1, R2, R3, ADDR)                                          \
    asm volatile("ldmatrix.sync.aligned.m8n8.x4.shared.b16 {%0,%1,%2,%3}, [%4];" \
                 : "=r"(R0), "=r"(R1), "=r"(R2), "=r"(R3) : "r"(ADDR))

#define MMA_TF32(C, A, B)                                              \
    asm volatile(                                                      \
        "mma.sync.aligned.m16n8k8.row.col.f32.tf32.tf32.f32 "          \
        "{%0,%1,%2,%3}, {%4,%5,%6,%7}, {%8,%9}, {%0,%1,%2,%3};"        \
        : "+f"((C)[0]), "+f"((C)[1]), "+f"((C)[2]), "+f"((C)[3])       \
        : "r"((A)[0]), "r"((A)[1]), "r"((A)[2]), "r"((A)[3]),          \
          "r"((B)[0]), "r"((B)[1]))

__device__ __forceinline__ float sigmoidf_(float x) { return 1.0f / (1.0f + expf(-x)); }

// ---------------- merged adjacency builder (1 launch, coalesced both parts) ----------------
#define LIT_BLOCKS ((NLITS + 7) / 8)
#define CLS_BLOCKS2 ((NCLS + 255) / 256)

__global__ void build_both_kernel(const float* __restrict__ M) {
    if (blockIdx.x < LIT_BLOCKS) {
        int lane = threadIdx.x & 31;
        int wslot = threadIdx.x >> 5;
        int l = blockIdx.x * 8 + wslot;
        if (l >= NLITS) return;
        const float* row = M + (size_t)l * NCLS;
        int cnt = 0;
        for (int c0 = 0; c0 < NCLS; c0 += 32) {
            float v = row[c0 + lane];
            unsigned mask = __ballot_sync(0xffffffffu, v != 0.0f);
            if (v != 0.0f) {
                int pos = cnt + __popc(mask & ((1u << lane) - 1u));
                if (pos < LIT_STRIDE) g_lit_idx[(size_t)l * LIT_STRIDE + pos] = c0 + lane;
            }
            cnt += __popc(mask);
        }
        if (lane == 0) g_lit_len[l] = cnt < LIT_STRIDE ? cnt : LIT_STRIDE;
    } else {
        // one thread per clause; warp reads 32 consecutive clause entries per
        // literal row -> 128B coalesced (replaces the 32KB-strided column scan)
        int c = (blockIdx.x - LIT_BLOCKS) * 256 + threadIdx.x;
        if (c >= NCLS) return;
        int cnt = 0;
        for (int l = 0; l < NLITS; l++) {
            float v = M[(size_t)l * NCLS + c];
            if (v != 0.0f) {
                if (cnt < CLS_STRIDE) g_cls_idx[(size_t)c * CLS_STRIDE + cnt] = l;
                cnt++;
            }
        }
        g_cls_len[c] = cnt < CLS_STRIDE ? cnt : CLS_STRIDE;
    }
}

// ---------------- consolidated weight splitter (1 launch, 12 weights) ----------------
// perm=1: output row n takes source row (n&3)*E + (n>>2)  (gate-interleave; K=E)
struct WSplit { const float* in; float* hi; float* lo; int rows, K, KP, perm; };
struct WSplitAll { WSplit w[12]; };

__global__ void split_all_kernel(WSplitAll all) {
    const WSplit w = all.w[blockIdx.y];
    int i = blockIdx.x * blockDim.x + threadIdx.x;
    if (i >= w.rows * w.KP) return;
    int r = i / w.KP, k = i - r * w.KP;
    int sr = w.perm ? ((r & 3) * E + (r >> 2)) : r;
    float v = (k < w.K) ? w.in[(size_t)sr * w.K + k] : 0.0f;
    uint32_t h, l;
    tf32_split(v, h, l);
    w.hi[i] = __uint_as_float(h);
    w.lo[i] = __uint_as_float(l);
}

// ---------------- state init ----------------
__global__ void init_states_kernel(const float* __restrict__ L_init,
                                   const float* __restrict__ C_init) {
    int i = blockIdx.x * blockDim.x + threadIdx.x;
    const int totL = NLITS * E;
    if (i < totL) {
        g_LhA[i] = L_init[i & (E - 1)]; g_Lc[i] = 0.0f;
    } else if (i < totL + NCLS * E) {
        int j = i - totL;
        g_ChA[j] = C_init[j & (E - 1)]; g_Cc[j] = 0.0f;
    }
}

// ---------------- tf32x3 mma GEMM, 3-stage cp.async, optional fused LSTM epilogue ----
struct GP {
    const float* A[2];
    const float* Bh[2];
    const float* Bl[2];
    const float* bias;     // LSTM: original gate-major bias (len 512)
    float* out;            // normal path output
    float* hout;           // LSTM path: new h
    float* cst;            // LSTM path: c state (in/out)
    int M;
    int nseg;
};

template <bool RELU, bool LSTM_EPI>
__global__ void __launch_bounds__(256, 3) gemm_tf32x3_kernel(GP p0, GP p1, int N, int K, int opitch)
{
    const GP p = (blockIdx.z == 0) ? p0 : p1;
    const int m0 = blockIdx.y * 128;
    if (m0 >= p.M) return;
    const int n0 = blockIdx.x * 64;

    extern __shared__ char smem[];
    const uint32_t sb = smem_u32(smem);

    const int tid = threadIdx.x;
    const int lane = tid & 31;
    const int wid = tid >> 5;
    const int wm0 = (wid & 3) * 32;
    const int wn0 = (wid >> 2) * 32;
    const int grp = lane >> 2;
    const int q = lane & 3;
    const int sel = lane >> 3;

    const int ntiles = K / BK;
    const int total = ntiles * p.nseg;

    float c[2][4][4];
#pragma unroll
    for (int a = 0; a < 2; a++)
#pragma unroll
        for (int b = 0; b < 4; b++)
#pragma unroll
            for (int d = 0; d < 4; d++) c[a][b][d] = 0.0f;

    auto load_stage = [&](int ti, int stage) {
        const int seg = ti / ntiles;
        const int k0 = (ti - seg * ntiles) * BK;
        const float* Ap  = p.A[seg];
        const float* Bph = p.Bh[seg];
        const float* Bpl = p.Bl[seg];
        const uint32_t base = sb + stage * STAGE_BYTES;
#pragma unroll
        for (int i = 0; i < 2; i++) {
            int cid = tid + i * 256;
            int row = cid >> 2;
            int col = cid & 3;
            bool va = (m0 + row < p.M);
            int ra = va ? (m0 + row) : 0;
            cp16(base + row * SPB + col * 16, Ap + (size_t)ra * K + k0 + col * 4, va);
        }
        {
            int row = tid >> 2;
            int col = tid & 3;
            bool vb = (n0 + row < N);
            int rb = vb ? (n0 + row) : 0;
            uint32_t doff = row * SPB + col * 16;
            cp16(base + TILEB_A + doff,           Bph + (size_t)rb * K + k0 + col * 4, vb);
            cp16(base + TILEB_A + TILEB_B + doff, Bpl + (size_t)rb * K + k0 + col * 4, vb);
        }
        CP_COMMIT();
    };

    load_stage(0, 0);
    if (total > 1) load_stage(1, 1);
    else CP_COMMIT();

    for (int t = 0; t < total; t++) {
        if (t + 1 < total) { CP_WAIT1(); } else { CP_WAIT0(); }
        __syncthreads();

        if (t + 2 < total) load_stage(t + 2, (t + 2) % STAGES);

        const int st = (t % STAGES) * STAGE_BYTES;
        const uint32_t Ab  = sb + st;
        const uint32_t Bhb = sb + st + TILEB_A;
        const uint32_t Blb = sb + st + TILEB_A + TILEB_B;

#pragma unroll
        for (int kk = 0; kk < 2; kk++) {
            const int cb = kk * 8;

            uint32_t ah[2][4], al[2][4];
#pragma unroll
            for (int mt = 0; mt < 2; mt++) {
                int rowa = wm0 + mt * 16 + (lane & 7) + ((sel & 1) << 3);
                int cola = cb + ((sel >> 1) << 2);
                uint32_t r0, r1, r2, r3;
                LDSM4(r0, r1, r2, r3, Ab + rowa * SPB + cola * 4);
                tf32_split(__uint_as_float(r0), ah[mt][0], al[mt][0]);
                tf32_split(__uint_as_float(r1), ah[mt][1], al[mt][1]);
                tf32_split(__uint_as_float(r2), ah[mt][2], al[mt][2]);
                tf32_split(__uint_as_float(r3), ah[mt][3], al[mt][3]);
            }

            uint32_t bhf[2][4], blf[2][4];
#pragma unroll
            for (int ngp = 0; ngp < 2; ngp++) {
                int rowb = wn0 + ngp * 16 + (lane & 7) + ((sel >> 1) << 3);
                int colb = cb + ((sel & 1) << 2);
                LDSM4(bhf[ngp][0], bhf[ngp][1], bhf[ngp][2], bhf[ngp][3],
                      Bhb + rowb * SPB + colb * 4);
                LDSM4(blf[ngp][0], blf[ngp][1], blf[ngp][2], blf[ngp][3],
                      Blb + rowb * SPB + colb * 4);
            }

#pragma unroll
            for (int mt = 0; mt < 2; mt++)
#pragma unroll
                for (int ngp = 0; ngp < 2; ngp++) {
                    MMA_TF32(c[mt][2 * ngp],     ah[mt], (&bhf[ngp][0]));
                    MMA_TF32(c[mt][2 * ngp + 1], ah[mt], (&bhf[ngp][2]));
                }
#pragma unroll
            for (int mt = 0; mt < 2; mt++)
#pragma unroll
                for (int ngp = 0; ngp < 2; ngp++) {
                    MMA_TF32(c[mt][2 * ngp],     ah[mt], (&blf[ngp][0]));
                    MMA_TF32(c[mt][2 * ngp + 1], ah[mt], (&blf[ngp][2]));
                }
#pragma unroll
            for (int mt = 0; mt < 2; mt++)
#pragma unroll
                for (int ngp = 0; ngp < 2; ngp++) {
                    MMA_TF32(c[mt][2 * ngp],     al[mt], (&bhf[ngp][0]));
                    MMA_TF32(c[mt][2 * ngp + 1], al[mt], (&bhf[ngp][2]));
                }
        }
    }

    if (LSTM_EPI) {
        // smem-staged, lane-balanced LSTM epilogue. Block owns rows m0..m0+127
        // and j columns jbase..jbase+15 (N-tile 64 = 16 js x 4 gates).
        float* sc = (float*)smem;            // c tile [128][16]
        float* sh = ((float*)smem) + 2048;   // h tile [128][16]
        const int jbase = n0 >> 2;
        __syncthreads();   // mma loop complete in all warps; stage buffers reusable
        for (int idx = tid; idx < 2048; idx += 256) {
            int rrow = idx >> 4, jj = idx & 15;
            int grow = m0 + rrow;
            sc[idx] = (grow < p.M) ? p.cst[(size_t)grow * E + jbase + jj] : 0.0f;
        }
        __syncthreads();
#pragma unroll
        for (int mt = 0; mt < 2; mt++) {
#pragma unroll
            for (int ng = 0; ng < 4; ng++) {
                int lcol = wn0 + ng * 8 + q * 2;     // local col in N-tile
                int lj = lcol >> 2;                   // 0..15
                int gsel = lcol & 3;                  // 0 (i,f) or 2 (g,o)
                int jglob = jbase + lj;
                float b0 = p.bias[gsel * E + jglob];
                float b1 = p.bias[(gsel + 1) * E + jglob];
                float v00 = c[mt][ng][0] + b0;   // half0, gate gsel
                float v01 = c[mt][ng][1] + b1;   // half0, gate gsel+1
                float v10 = c[mt][ng][2] + b0;   // half1
                float v11 = c[mt][ng][3] + b1;
                float e00 = __shfl_xor_sync(0xffffffffu, v00, 1);
                float e01 = __shfl_xor_sync(0xffffffffu, v01, 1);
                float e10 = __shfl_xor_sync(0xffffffffu, v10, 1);
                float e11 = __shfl_xor_sync(0xffffffffu, v11, 1);
                float iv, fv, gv, ov; int half;
                if ((lane & 1) == 0) { iv = v00; fv = v01; gv = e00; ov = e01; half = 0; }
                else                 { iv = e10; fv = e11; gv = v10; ov = v11; half = 1; }
                int lrow = wm0 + mt * 16 + grp + half * 8;
                float ig = sigmoidf_(iv);
                float fg = sigmoidf_(fv);
                float gg = tanhf(gv);
                float og = sigmoidf_(ov);
                int sidx = lrow * 16 + lj;
                float c2 = fg * sc[sidx] + ig * gg;
                sc[sidx] = c2;
                sh[sidx] = og * tanhf(c2);
            }
        }
        __syncthreads();
        for (int idx = tid; idx < 2048; idx += 256) {
            int rrow = idx >> 4, jj = idx & 15;
            int grow = m0 + rrow;
            if (grow < p.M) {
                p.cst[(size_t)grow * E + jbase + jj]  = sc[idx];
                p.hout[(size_t)grow * E + jbase + jj] = sh[idx];
            }
        }
    } else {
#pragma unroll
        for (int mt = 0; mt < 2; mt++) {
#pragma unroll
            for (int ng = 0; ng < 4; ng++) {
                int col = n0 + wn0 + ng * 8 + q * 2;
                if (col >= N) continue;
                float b0 = p.bias[col], b1 = p.bias[col + 1];
#pragma unroll
                for (int half = 0; half < 2; half++) {
                    int row = m0 + wm0 + mt * 16 + grp + half * 8;
                    if (row >= p.M) continue;
                    float v0 = c[mt][ng][half * 2 + 0] + b0;
                    float v1 = c[mt][ng][half * 2 + 1] + b1;
                    if (RELU) { v0 = fmaxf(v0, 0.0f); v1 = fmaxf(v1, 0.0f); }
                    *(float2*)(p.out + (size_t)row * opitch + col) = make_float2(v0, v1);
                }
            }
        }
    }
}

template <bool RELU, bool LSTM_EPI>
static inline void launch_gemm(GP p0, GP p1, int nz, int N, int K, int opitch) {
    cudaFuncSetAttribute(gemm_tf32x3_kernel<RELU, LSTM_EPI>,
                         cudaFuncAttributeMaxDynamicSharedMemorySize, GEMM_SMEM);
    int mmax = p0.M;
    if (nz > 1 && p1.M > mmax) mmax = p1.M;
    dim3 grid((N + 63) / 64, (mmax + 127) / 128, nz);
    gemm_tf32x3_kernel<RELU, LSTM_EPI><<<grid, 256, GEMM_SMEM>>>(p0, p1, N, K, opitch);
}

// ---------------- combined SpMM gather (both directions) ----------------
__global__ void spmm_both_kernel() {
    int r = (blockIdx.x * blockDim.x + threadIdx.x) >> 5;
    if (r >= NCLS + NLITS) return;
    int lane = threadIdx.x & 31;

    const int* lst; int n; const float* in; float* outp;
    if (r < NCLS) {
        lst = g_cls_idx + (size_t)r * CLS_STRIDE; n = g_cls_len[r];
        in = g_mlpL; outp = g_msgC + (size_t)r * E;
    } else {
        int rr = r - NCLS;
        lst = g_lit_idx + (size_t)rr * LIT_STRIDE; n = g_lit_len[rr];
        in = g_mlpC; outp = g_msgL + (size_t)rr * E;
    }

    float4 acc = make_float4(0.f, 0.f, 0.f, 0.f);
    int j = 0;
    for (; j + 4 <= n; j += 4) {
        int i0 = lst[j], i1 = lst[j + 1], i2 = lst[j + 2], i3 = lst[j + 3];
        float4 v0 = ((const float4*)(in + (size_t)i0 * E))[lane];
        float4 v1 = ((const float4*)(in + (size_t)i1 * E))[lane];
        float4 v2 = ((const float4*)(in + (size_t)i2 * E))[lane];
        float4 v3 = ((const float4*)(in + (size_t)i3 * E))[lane];
        acc.x += v0.x + v1.x + v2.x + v3.x;
        acc.y += v0.y + v1.y + v2.y + v3.y;
        acc.z += v0.z + v1.z + v2.z + v3.z;
        acc.w += v0.w + v1.w + v2.w + v3.w;
    }
    for (; j < n; j++) {
        float4 v = ((const float4*)(in + (size_t)lst[j] * E))[lane];
        acc.x += v.x; acc.y += v.y; acc.z += v.z; acc.w += v.w;
    }
    ((float4*)outp)[lane] = acc;
}

// ---------------- vote + reduction ----------------
__global__ void vote_partial_kernel(const float* __restrict__ X2,
                                    const float* __restrict__ W3,
                                    const float* __restrict__ b3,
                                    float* __restrict__ partials) {
    int warp = (blockIdx.x * blockDim.x + threadIdx.x) >> 5;
    int lane = threadIdx.x & 31;
    float vote = 0.0f;
    if (warp < NLITS) {
        const float* x = X2 + (size_t)warp * H2P;
        float s = 0.0f;
        for (int jj = lane; jj < H2; jj += 32) s += x[jj] * W3[jj];
#pragma unroll
        for (int o = 16; o; o >>= 1) s += __shfl_down_sync(0xffffffffu, s, o);
        if (lane == 0) vote = sigmoidf_(s + b3[0]);
    }
    __shared__ float sm[8];
    if (lane == 0) sm[threadIdx.x >> 5] = vote;
    __syncthreads();
    if (threadIdx.x == 0) {
        float t = 0.0f;
        for (int w = 0; w < 8; w++) t += sm[w];
        partials[blockIdx.x] = t;
    }
}

__global__ void finalize_kernel(const float* __restrict__ partials, int n,
                                float* __restrict__ out) {
    __shared__ float sm[512];
    float s = 0.0f;
    for (int i = threadIdx.x; i < n; i += blockDim.x) s += partials[i];
    sm[threadIdx.x] = s;
    __syncthreads();
    for (int o = 256; o; o >>= 1) {
        if (threadIdx.x < o) sm[threadIdx.x] += sm[threadIdx.x + o];
        __syncthreads();
    }
    if (threadIdx.x == 0) {
        float avg = sm[0] / (float)NLITS;
        out[0] = logf(avg / (1.0f - avg));
    }
}

// ---------------- host ----------------
#define SYM(var, sym) cudaGetSymbolAddress((void**)&var, sym)

extern "C" void kernel_launch(void* const* d_in, const int* in_sizes, int n_in,
                              void* d_out, int out_size) {
    const float* M      = (const float*)d_in[0];
    const float* L_init = (const float*)d_in[1];
    const float* C_init = (const float*)d_in[2];
    const float* LC_W1 = (const float*)d_in[3];  const float* LC_b1 = (const float*)d_in[4];
    const float* LC_W2 = (const float*)d_in[5];  const float* LC_b2 = (const float*)d_in[6];
    const float* LC_W3 = (const float*)d_in[7];  const float* LC_b3 = (const float*)d_in[8];
    const float* CL_W1 = (const float*)d_in[9];  const float* CL_b1 = (const float*)d_in[10];
    const float* CL_W2 = (const float*)d_in[11]; const float* CL_b2 = (const float*)d_in[12];
    const float* CL_W3 = (const float*)d_in[13]; const float* CL_b3 = (const float*)d_in[14];
    const float* L_Wih = (const float*)d_in[15]; const float* L_Whh = (const float*)d_in[16];
    const float* L_b   = (const float*)d_in[17];
    const float* C_Wih = (const float*)d_in[18]; const float* C_Whh = (const float*)d_in[19];
    const float* C_b   = (const float*)d_in[20];
    const float* V_W1 = (const float*)d_in[21];  const float* V_b1 = (const float*)d_in[22];
    const float* V_W2 = (const float*)d_in[23];  const float* V_b2 = (const float*)d_in[24];
    const float* V_W3 = (const float*)d_in[25];  const float* V_b3 = (const float*)d_in[26];
    float* out = (float*)d_out;

    float *LhA, *LhB, *Lc, *ChA, *ChB, *Cc, *b1L, *b1C, *b2L, *b2C;
    float *mlpL, *mlpC, *msgL, *msgC, *partials;
    float *LC1h,*LC1l,*LC2h,*LC2l,*LC3h,*LC3l,*CL1h,*CL1l,*CL2h,*CL2l,*CL3h,*CL3l;
    float *CWih,*CWil,*CWhh,*CWhl,*LWih,*LWil,*LWhh,*LWhl,*VW1h,*VW1l,*VW2h,*VW2l;
    SYM(LhA, g_LhA); SYM(LhB, g_LhB); SYM(Lc, g_Lc);
    SYM(ChA, g_ChA); SYM(ChB, g_ChB); SYM(Cc, g_Cc);
    SYM(b1L, g_b1L); SYM(b1C, g_b1C); SYM(b2L, g_b2L); SYM(b2C, g_b2C);
    SYM(mlpL, g_mlpL); SYM(mlpC, g_mlpC); SYM(msgL, g_msgL); SYM(msgC, g_msgC);
    SYM(partials, g_partials);
    SYM(LC1h, g_LC1h); SYM(LC1l, g_LC1l); SYM(LC2h, g_LC2h); SYM(LC2l, g_LC2l);
    SYM(LC3h, g_LC3h); SYM(LC3l, g_LC3l);
    SYM(CL1h, g_CL1h); SYM(CL1l, g_CL1l); SYM(CL2h, g_CL2h); SYM(CL2l, g_CL2l);
    SYM(CL3h, g_CL3h); SYM(CL3l, g_CL3l);
    SYM(CWih, g_CWih); SYM(CWil, g_CWil); SYM(CWhh, g_CWhh); SYM(CWhl, g_CWhl);
    SYM(LWih, g_LWih); SYM(LWil, g_LWil); SYM(LWhh, g_LWhh); SYM(LWhl, g_LWhl);
    SYM(VW1h, g_VW1h); SYM(VW1l, g_VW1l); SYM(VW2h, g_VW2h); SYM(VW2l, g_VW2l);

    // ---- setup: 3 launches ----
    build_both_kernel<<<LIT_BLOCKS + CLS_BLOCKS2, 256>>>(M);

    WSplitAll ws = {{
        {LC_W1, LC1h, LC1l, H1, E,  E,   0},
        {LC_W2, LC2h, LC2l, H2, H1, H1,  0},
        {LC_W3, LC3h, LC3l, E,  H2, H2P, 0},
        {CL_W1, CL1h, CL1l, H1, E,  E,   0},
        {CL_W2, CL2h, CL2l, H2, H1, H1,  0},
        {CL_W3, CL3h, CL3l, E,  H2, H2P, 0},
        {C_Wih, CWih, CWil, NG, E,  E,   1},   // gate-interleaved
        {C_Whh, CWhh, CWhl, NG, E,  E,   1},
        {L_Wih, LWih, LWil, NG, E,  E,   1},
        {L_Whh, LWhh, LWhl, NG, E,  E,   1},
        {V_W1,  VW1h, VW1l, H1, E,  E,   0},
        {V_W2,  VW2h, VW2l, H2, H1, H1,  0},
    }};
    dim3 sg((H2 * H1 + 255) / 256, 12);
    split_all_kernel<<<sg, 256>>>(ws);

    init_states_kernel<<<((NLITS + NCLS) * E + 255) / 256, 256>>>(L_init, C_init);

    GP dummy = {};

    for (int t = 0; t < TSTEPS; t++) {
        float* LhC = (t & 1) ? LhB : LhA;   // current h (read)
        float* LhN = (t & 1) ? LhA : LhB;   // next h (written by fused epilogue)
        float* ChC = (t & 1) ? ChB : ChA;
        float* ChN = (t & 1) ? ChA : ChB;

        // MLP L1 (relu)
        GP a1 = {{LhC}, {LC1h}, {LC1l}, LC_b1, b1L, nullptr, nullptr, NLITS, 1};
        GP b1 = {{ChC}, {CL1h}, {CL1l}, CL_b1, b1C, nullptr, nullptr, NCLS, 1};
        launch_gemm<true, false>(a1, b1, 2, H1, E, H1);

        // MLP L2 (relu)
        GP a2 = {{b1L}, {LC2h}, {LC2l}, LC_b2, b2L, nullptr, nullptr, NLITS, 1};
        GP b2 = {{b1C}, {CL2h}, {CL2l}, CL_b2, b2C, nullptr, nullptr, NCLS, 1};
        launch_gemm<true, false>(a2, b2, 2, H2, H1, H2P);

        // MLP L3 (no relu)
        GP a3 = {{b2L}, {LC3h}, {LC3l}, LC_b3, mlpL, nullptr, nullptr, NLITS, 1};
        GP b3 = {{b2C}, {CL3h}, {CL3l}, CL_b3, mlpC, nullptr, nullptr, NCLS, 1};
        launch_gemm<false, false>(a3, b3, 2, E, H2P, E);

        // sparse aggregation
        spmm_both_kernel<<<(NCLS + NLITS + 7) / 8, 256>>>();

        // LSTM gates GEMM + fused, smem-staged cell update
        GP ga = {{msgC, ChC}, {CWih, CWhh}, {CWil, CWhl}, C_b,
                 nullptr, ChN, Cc, NCLS, 2};
        GP gb = {{msgL, LhC}, {LWih, LWhh}, {LWil, LWhl}, L_b,
                 nullptr, LhN, Lc, NLITS, 2};
        launch_gemm<false, true>(ga, gb, 2, NG, E, NG);
    }

    // final h is in buffer A (TSTEPS even)
    GP v1 = {{LhA}, {VW1h}, {VW1l}, V_b1, b1L, nullptr, nullptr, NLITS, 1};
    launch_gemm<true, false>(v1, dummy, 1, H1, E, H1);
    GP v2 = {{b1L}, {VW2h}, {VW2l}, V_b2, b2L, nullptr, nullptr, NLITS, 1};
    launch_gemm<true, false>(v2, dummy, 1, H2, H1, H2P);
    vote_partial_kernel<<<VOTE_BLOCKS, 256>>>(b2L, V_W3, V_b3, partials);
    finalize_kernel<<<1, 512>>>(partials, VOTE_BLOCKS, out);
}

// round 15
// speedup vs baseline: 1.2075x; 1.2075x over previous
#include <cuda_runtime.h>
#include <math.h>
#include <stdint.h>

// ---------------- problem constants ----------------
#define NLITS 4000
#define NCLS  8000
#define E     128
#define H1    400
#define H2    200
#define K2P   416          // H1 padded to multiple of 32
#define K3P   224          // H2 padded to multiple of 32
#define NG    512          // 4*E LSTM gates
#define TSTEPS 30
#define LIT_STRIDE 512
#define CLS_STRIDE 256
#define VOTE_BLOCKS ((NLITS + 7) / 8)

// GEMM tiling: block tile 128(M) x 64(N), 8 warps (4 over M x 2 over N), BK=32
#define BK 32
#define SPBB 144                 // smem row stride bytes (32 floats + 4 pad)
#define TILEB_A (128 * SPBB)     // 18432 B
#define TILEB_B (64 * SPBB)      // 9216 B
#define STAGE_BYTES (TILEB_A + 2 * TILEB_B)   // A, Bh, Bl = 36864 B
#define STAGES 3
#define GEMM_SMEM (STAGES * STAGE_BYTES)      // 110592 B; 2 blocks/SM

// ---------------- device scratch (static, BSS zero-init, allocation-free) ----------------
__device__ float g_Lh[NLITS * E], g_Lc[NLITS * E];
__device__ float g_Ch[NCLS * E],  g_Cc[NCLS * E];
__device__ float g_b1L[NLITS * K2P], g_b1C[NCLS * K2P];   // pad cols [400,416) stay 0
__device__ float g_b2L[NLITS * K3P], g_b2C[NCLS * K3P];   // pad cols [200,224) stay 0
__device__ float g_mlpL[NLITS * E],  g_mlpC[NCLS * E];
__device__ float g_msgL[NLITS * E],  g_msgC[NCLS * E];
__device__ float g_gatesC[NCLS * NG], g_gatesL[NLITS * NG];

// pre-split weights (tf32-valued fp32 hi/lo), K padded to mult of 32
__device__ float g_LC1h[H1 * E],    g_LC1l[H1 * E];
__device__ float g_LC2h[H2 * K2P],  g_LC2l[H2 * K2P];
__device__ float g_LC3h[E * K3P],   g_LC3l[E * K3P];
__device__ float g_CL1h[H1 * E],    g_CL1l[H1 * E];
__device__ float g_CL2h[H2 * K2P],  g_CL2l[H2 * K2P];
__device__ float g_CL3h[E * K3P],   g_CL3l[E * K3P];
__device__ float g_CWih[NG * E],    g_CWil[NG * E];
__device__ float g_CWhh[NG * E],    g_CWhl[NG * E];
__device__ float g_LWih[NG * E],    g_LWil[NG * E];
__device__ float g_LWhh[NG * E],    g_LWhl[NG * E];
__device__ float g_VW1h[H1 * E],    g_VW1l[H1 * E];
__device__ float g_VW2h[H2 * K2P],  g_VW2l[H2 * K2P];

__device__ int   g_lit_idx[(size_t)NLITS * LIT_STRIDE];
__device__ int   g_lit_len[NLITS];
__device__ int   g_cls_idx[(size_t)NCLS * CLS_STRIDE];
__device__ int   g_cls_len[NCLS];
__device__ float g_partials[VOTE_BLOCKS];

// ---------------- helpers ----------------
__device__ __forceinline__ unsigned smem_u32(const void* p) {
    return (unsigned)__cvta_generic_to_shared(p);
}
__device__ __forceinline__ void tf32_split(float v, uint32_t& h, uint32_t& l) {
    asm("cvt.rna.tf32.f32 %0, %1;" : "=r"(h) : "f"(v));
    float r = v - __uint_as_float(h);
    asm("cvt.rna.tf32.f32 %0, %1;" : "=r"(l) : "f"(r));
}
__device__ __forceinline__ void cp16(uint32_t dst, const void* src, bool valid) {
    int sz = valid ? 16 : 0;
    asm volatile("cp.async.cg.shared.global [%0], [%1], 16, %2;"
                 :: "r"(dst), "l"(src), "r"(sz) : "memory");
}
#define CP_COMMIT() asm volatile("cp.async.commit_group;" ::: "memory")
#define CP_WAIT1()  asm volatile("cp.async.wait_group 1;" ::: "memory")
#define CP_WAIT0()  asm volatile("cp.async.wait_group 0;" ::: "memory")

#define LDSM4(R0, R1, R2, R3, ADDR)                                          \
    asm volatile("ldmatrix.sync.aligned.m8n8.x4.shared.b16 {%0,%1,%2,%3}, [%4];" \
                 : "=r"(R0), "=r"(R1), "=r"(R2), "=r"(R3) : "r"(ADDR))

#define MMA_TF32(C, A, B)                                              \
    asm volatile(                                                      \
        "mma.sync.aligned.m16n8k8.row.col.f32.tf32.tf32.f32 "          \
        "{%0,%1,%2,%3}, {%4,%5,%6,%7}, {%8,%9}, {%0,%1,%2,%3};"        \
        : "+f"((C)[0]), "+f"((C)[1]), "+f"((C)[2]), "+f"((C)[3])       \
        : "r"((A)[0]), "r"((A)[1]), "r"((A)[2]), "r"((A)[3]),          \
          "r"((B)[0]), "r"((B)[1]))

__device__ __forceinline__ float sigmoidf_(float x) { return 1.0f / (1.0f + expf(-x)); }

// ---------------- merged adjacency builder (1 launch) ----------------
#define LIT_BLOCKS ((NLITS + 7) / 8)
#define CLS_BLOCKS ((NCLS + 7) / 8)

__global__ void build_both_kernel(const float* __restrict__ M) {
    int lane = threadIdx.x & 31;
    int wslot = threadIdx.x >> 5;
    if (blockIdx.x < LIT_BLOCKS) {
        int l = blockIdx.x * 8 + wslot;
        if (l >= NLITS) return;
        const float* row = M + (size_t)l * NCLS;
        int cnt = 0;
        for (int c0 = 0; c0 < NCLS; c0 += 32) {
            float v = row[c0 + lane];
            unsigned mask = __ballot_sync(0xffffffffu, v != 0.0f);
            if (v != 0.0f) {
                int pos = cnt + __popc(mask & ((1u << lane) - 1u));
                if (pos < LIT_STRIDE) g_lit_idx[(size_t)l * LIT_STRIDE + pos] = c0 + lane;
            }
            cnt += __popc(mask);
        }
        if (lane == 0) g_lit_len[l] = cnt < LIT_STRIDE ? cnt : LIT_STRIDE;
    } else {
        int c = (blockIdx.x - LIT_BLOCKS) * 8 + wslot;
        if (c >= NCLS) return;
        int cnt = 0;
        for (int l0 = 0; l0 < NLITS; l0 += 32) {
            float v = M[(size_t)(l0 + lane) * NCLS + c];
            unsigned mask = __ballot_sync(0xffffffffu, v != 0.0f);
            if (v != 0.0f) {
                int pos = cnt + __popc(mask & ((1u << lane) - 1u));
                if (pos < CLS_STRIDE) g_cls_idx[(size_t)c * CLS_STRIDE + pos] = l0 + lane;
            }
            cnt += __popc(mask);
        }
        if (lane == 0) g_cls_len[c] = cnt < CLS_STRIDE ? cnt : CLS_STRIDE;
    }
}

// ---------------- consolidated weight splitter (1 launch, 12 weights) ----------------
struct WSplit { const float* in; float* hi; float* lo; int rows, K, KP; };
struct WSplitAll { WSplit w[12]; };

__global__ void split_all_kernel(WSplitAll all) {
    const WSplit w = all.w[blockIdx.y];
    int i = blockIdx.x * blockDim.x + threadIdx.x;
    if (i >= w.rows * w.KP) return;
    int r = i / w.KP, k = i - r * w.KP;
    float v = (k < w.K) ? w.in[(size_t)r * w.K + k] : 0.0f;
    uint32_t h, l;
    tf32_split(v, h, l);
    w.hi[i] = __uint_as_float(h);
    w.lo[i] = __uint_as_float(l);
}

// ---------------- state init ----------------
__global__ void init_states_kernel(const float* __restrict__ L_init,
                                   const float* __restrict__ C_init) {
    int i = blockIdx.x * blockDim.x + threadIdx.x;
    const int totL = NLITS * E;
    if (i < totL) {
        g_Lh[i] = L_init[i & (E - 1)]; g_Lc[i] = 0.0f;
    } else if (i < totL + NCLS * E) {
        int j = i - totL;
        g_Ch[j] = C_init[j & (E - 1)]; g_Cc[j] = 0.0f;
    }
}

// ---------------- tf32x3 mma GEMM, 3-stage cp.async pipeline, BK=32 ----------------
struct GP {
    const float* A[2];
    const float* Bh[2];
    const float* Bl[2];
    const float* bias;
    float* out;
    int M;
    int nseg;
};

template <bool RELU>
__global__ void __launch_bounds__(256, 2) gemm_tf32x3_kernel(GP p0, GP p1, int N, int K, int opitch)
{
    const GP p = (blockIdx.z == 0) ? p0 : p1;
    const int m0 = blockIdx.y * 128;
    if (m0 >= p.M) return;
    const int n0 = blockIdx.x * 64;

    extern __shared__ char smem[];
    const uint32_t sb = smem_u32(smem);

    const int tid = threadIdx.x;
    const int lane = tid & 31;
    const int wid = tid >> 5;
    const int wm0 = (wid & 3) * 32;
    const int wn0 = (wid >> 2) * 32;
    const int grp = lane >> 2;
    const int q = lane & 3;
    const int sel = lane >> 3;

    const int ntiles = K >> 5;          // BK=32
    const int total = ntiles * p.nseg;

    float c[2][4][4];
#pragma unroll
    for (int a = 0; a < 2; a++)
#pragma unroll
        for (int b = 0; b < 4; b++)
#pragma unroll
            for (int d = 0; d < 4; d++) c[a][b][d] = 0.0f;

    auto load_stage = [&](int ti, int stage) {
        const int seg = ti / ntiles;
        const int k0 = (ti - seg * ntiles) << 5;
        const float* Ap  = p.A[seg];
        const float* Bph = p.Bh[seg];
        const float* Bpl = p.Bl[seg];
        const uint32_t base = sb + stage * STAGE_BYTES;
        // A: 128 rows x 8 chunks = 1024 cp16
#pragma unroll
        for (int i = 0; i < 4; i++) {
            int cid = tid + i * 256;
            int row = cid >> 3;
            int ch = cid & 7;
            bool va = (m0 + row < p.M);
            int ra = va ? (m0 + row) : 0;
            cp16(base + row * SPBB + ch * 16, Ap + (size_t)ra * K + k0 + ch * 4, va);
        }
        // Bh/Bl: 64 rows x 8 chunks = 512 cp16 each
#pragma unroll
        for (int i = 0; i < 2; i++) {
            int cid = tid + i * 256;
            int row = cid >> 3;
            int ch = cid & 7;
            bool vb = (n0 + row < N);
            int rb = vb ? (n0 + row) : 0;
            uint32_t doff = row * SPBB + ch * 16;
            size_t goff = (size_t)rb * K + k0 + ch * 4;
            cp16(base + TILEB_A + doff,           Bph + goff, vb);
            cp16(base + TILEB_A + TILEB_B + doff, Bpl + goff, vb);
        }
        CP_COMMIT();
    };

    load_stage(0, 0);
    if (total > 1) load_stage(1, 1);
    else CP_COMMIT();

    for (int t = 0; t < total; t++) {
        if (t + 1 < total) { CP_WAIT1(); } else { CP_WAIT0(); }
        __syncthreads();

        if (t + 2 < total) load_stage(t + 2, (t + 2) % STAGES);

        const int st = (t % STAGES) * STAGE_BYTES;
        const uint32_t Ab  = sb + st;
        const uint32_t Bhb = sb + st + TILEB_A;
        const uint32_t Blb = sb + st + TILEB_A + TILEB_B;

#pragma unroll
        for (int kk = 0; kk < 4; kk++) {
            const int cb = kk * 8;

            uint32_t ah[2][4], al[2][4];
#pragma unroll
            for (int mt = 0; mt < 2; mt++) {
                int rowa = wm0 + mt * 16 + (lane & 7) + ((sel & 1) << 3);
                int cola = cb + ((sel >> 1) << 2);
                uint32_t r0, r1, r2, r3;
                LDSM4(r0, r1, r2, r3, Ab + rowa * SPBB + cola * 4);
                tf32_split(__uint_as_float(r0), ah[mt][0], al[mt][0]);
                tf32_split(__uint_as_float(r1), ah[mt][1], al[mt][1]);
                tf32_split(__uint_as_float(r2), ah[mt][2], al[mt][2]);
                tf32_split(__uint_as_float(r3), ah[mt][3], al[mt][3]);
            }

            uint32_t bhf[2][4], blf[2][4];
#pragma unroll
            for (int ngp = 0; ngp < 2; ngp++) {
                int rowb = wn0 + ngp * 16 + (lane & 7) + ((sel >> 1) << 3);
                int colb = cb + ((sel & 1) << 2);
                LDSM4(bhf[ngp][0], bhf[ngp][1], bhf[ngp][2], bhf[ngp][3],
                      Bhb + rowb * SPBB + colb * 4);
                LDSM4(blf[ngp][0], blf[ngp][1], blf[ngp][2], blf[ngp][3],
                      Blb + rowb * SPBB + colb * 4);
            }

            // term-major mma issue (per-accumulator order: hh, hl, lh)
#pragma unroll
            for (int mt = 0; mt < 2; mt++)
#pragma unroll
                for (int ngp = 0; ngp < 2; ngp++) {
                    MMA_TF32(c[mt][2 * ngp],     ah[mt], (&bhf[ngp][0]));
                    MMA_TF32(c[mt][2 * ngp + 1], ah[mt], (&bhf[ngp][2]));
                }
#pragma unroll
            for (int mt = 0; mt < 2; mt++)
#pragma unroll
                for (int ngp = 0; ngp < 2; ngp++) {
                    MMA_TF32(c[mt][2 * ngp],     ah[mt], (&blf[ngp][0]));
                    MMA_TF32(c[mt][2 * ngp + 1], ah[mt], (&blf[ngp][2]));
                }
#pragma unroll
            for (int mt = 0; mt < 2; mt++)
#pragma unroll
                for (int ngp = 0; ngp < 2; ngp++) {
                    MMA_TF32(c[mt][2 * ngp],     al[mt], (&bhf[ngp][0]));
                    MMA_TF32(c[mt][2 * ngp + 1], al[mt], (&bhf[ngp][2]));
                }
        }
    }

    // epilogue: + bias, optional relu, guarded fp32 store
#pragma unroll
    for (int mt = 0; mt < 2; mt++) {
#pragma unroll
        for (int ng = 0; ng < 4; ng++) {
            int col = n0 + wn0 + ng * 8 + q * 2;
            if (col >= N) continue;
            float b0 = p.bias[col], b1 = p.bias[col + 1];
#pragma unroll
            for (int half = 0; half < 2; half++) {
                int row = m0 + wm0 + mt * 16 + grp + half * 8;
                if (row >= p.M) continue;
                float v0 = c[mt][ng][half * 2 + 0] + b0;
                float v1 = c[mt][ng][half * 2 + 1] + b1;
                if (RELU) { v0 = fmaxf(v0, 0.0f); v1 = fmaxf(v1, 0.0f); }
                *(float2*)(p.out + (size_t)row * opitch + col) = make_float2(v0, v1);
            }
        }
    }
}

template <bool RELU>
static inline void launch_gemm(GP p0, GP p1, int nz, int N, int K, int opitch) {
    cudaFuncSetAttribute(gemm_tf32x3_kernel<RELU>,
                         cudaFuncAttributeMaxDynamicSharedMemorySize, GEMM_SMEM);
    int mmax = p0.M;
    if (nz > 1 && p1.M > mmax) mmax = p1.M;
    dim3 grid((N + 63) / 64, (mmax + 127) / 128, nz);
    gemm_tf32x3_kernel<RELU><<<grid, 256, GEMM_SMEM>>>(p0, p1, N, K, opitch);
}

// ---------------- combined SpMM gather (both directions) ----------------
__global__ void spmm_both_kernel() {
    int r = (blockIdx.x * blockDim.x + threadIdx.x) >> 5;
    if (r >= NCLS + NLITS) return;
    int lane = threadIdx.x & 31;

    const int* lst; int n; const float* in; float* outp;
    if (r < NCLS) {
        lst = g_cls_idx + (size_t)r * CLS_STRIDE; n = g_cls_len[r];
        in = g_mlpL; outp = g_msgC + (size_t)r * E;
    } else {
        int rr = r - NCLS;
        lst = g_lit_idx + (size_t)rr * LIT_STRIDE; n = g_lit_len[rr];
        in = g_mlpC; outp = g_msgL + (size_t)rr * E;
    }

    float4 acc = make_float4(0.f, 0.f, 0.f, 0.f);
    int j = 0;
    for (; j + 4 <= n; j += 4) {
        int i0 = lst[j], i1 = lst[j + 1], i2 = lst[j + 2], i3 = lst[j + 3];
        float4 v0 = ((const float4*)(in + (size_t)i0 * E))[lane];
        float4 v1 = ((const float4*)(in + (size_t)i1 * E))[lane];
        float4 v2 = ((const float4*)(in + (size_t)i2 * E))[lane];
        float4 v3 = ((const float4*)(in + (size_t)i3 * E))[lane];
        acc.x += v0.x + v1.x + v2.x + v3.x;
        acc.y += v0.y + v1.y + v2.y + v3.y;
        acc.z += v0.z + v1.z + v2.z + v3.z;
        acc.w += v0.w + v1.w + v2.w + v3.w;
    }
    for (; j < n; j++) {
        float4 v = ((const float4*)(in + (size_t)lst[j] * E))[lane];
        acc.x += v.x; acc.y += v.y; acc.z += v.z; acc.w += v.w;
    }
    ((float4*)outp)[lane] = acc;
}

// ---------------- LSTM pointwise (both node types) ----------------
__global__ void lstm_pointwise_both() {
    int i = blockIdx.x * blockDim.x + threadIdx.x;
    const int totalC = NCLS * E;
    if (i >= totalC + NLITS * E) return;

    const float* gmat; float* cvec; float* hvec; int e;
    if (i < totalC) { gmat = g_gatesC; cvec = g_Cc; hvec = g_Ch; e = i; }
    else            { gmat = g_gatesL; cvec = g_Lc; hvec = g_Lh; e = i - totalC; }

    int row = e >> 7;
    int col = e & (E - 1);
    const float* gr = gmat + (size_t)row * NG;
    float ig = sigmoidf_(gr[col]);
    float fg = sigmoidf_(gr[E + col]);
    float gg = tanhf(gr[2 * E + col]);
    float og = sigmoidf_(gr[3 * E + col]);
    float c2 = fg * cvec[e] + ig * gg;
    cvec[e] = c2;
    hvec[e] = og * tanhf(c2);
}

// ---------------- vote + reduction ----------------
__global__ void vote_partial_kernel(const float* __restrict__ X2,
                                    const float* __restrict__ W3,
                                    const float* __restrict__ b3,
                                    float* __restrict__ partials) {
    int warp = (blockIdx.x * blockDim.x + threadIdx.x) >> 5;
    int lane = threadIdx.x & 31;
    float vote = 0.0f;
    if (warp < NLITS) {
        const float* x = X2 + (size_t)warp * K3P;
        float s = 0.0f;
        for (int jj = lane; jj < H2; jj += 32) s += x[jj] * W3[jj];
#pragma unroll
        for (int o = 16; o; o >>= 1) s += __shfl_down_sync(0xffffffffu, s, o);
        if (lane == 0) vote = sigmoidf_(s + b3[0]);
    }
    __shared__ float sm[8];
    if (lane == 0) sm[threadIdx.x >> 5] = vote;
    __syncthreads();
    if (threadIdx.x == 0) {
        float t = 0.0f;
        for (int w = 0; w < 8; w++) t += sm[w];
        partials[blockIdx.x] = t;
    }
}

__global__ void finalize_kernel(const float* __restrict__ partials, int n,
                                float* __restrict__ out) {
    __shared__ float sm[512];
    float s = 0.0f;
    for (int i = threadIdx.x; i < n; i += blockDim.x) s += partials[i];
    sm[threadIdx.x] = s;
    __syncthreads();
    for (int o = 256; o; o >>= 1) {
        if (threadIdx.x < o) sm[threadIdx.x] += sm[threadIdx.x + o];
        __syncthreads();
    }
    if (threadIdx.x == 0) {
        float avg = sm[0] / (float)NLITS;
        out[0] = logf(avg / (1.0f - avg));
    }
}

// ---------------- host ----------------
#define SYM(var, sym) cudaGetSymbolAddress((void**)&var, sym)

extern "C" void kernel_launch(void* const* d_in, const int* in_sizes, int n_in,
                              void* d_out, int out_size) {
    const float* M      = (const float*)d_in[0];
    const float* L_init = (const float*)d_in[1];
    const float* C_init = (const float*)d_in[2];
    const float* LC_W1 = (const float*)d_in[3];  const float* LC_b1 = (const float*)d_in[4];
    const float* LC_W2 = (const float*)d_in[5];  const float* LC_b2 = (const float*)d_in[6];
    const float* LC_W3 = (const float*)d_in[7];  const float* LC_b3 = (const float*)d_in[8];
    const float* CL_W1 = (const float*)d_in[9];  const float* CL_b1 = (const float*)d_in[10];
    const float* CL_W2 = (const float*)d_in[11]; const float* CL_b2 = (const float*)d_in[12];
    const float* CL_W3 = (const float*)d_in[13]; const float* CL_b3 = (const float*)d_in[14];
    const float* L_Wih = (const float*)d_in[15]; const float* L_Whh = (const float*)d_in[16];
    const float* L_b   = (const float*)d_in[17];
    const float* C_Wih = (const float*)d_in[18]; const float* C_Whh = (const float*)d_in[19];
    const float* C_b   = (const float*)d_in[20];
    const float* V_W1 = (const float*)d_in[21];  const float* V_b1 = (const float*)d_in[22];
    const float* V_W2 = (const float*)d_in[23];  const float* V_b2 = (const float*)d_in[24];
    const float* V_W3 = (const float*)d_in[25];  const float* V_b3 = (const float*)d_in[26];
    float* out = (float*)d_out;

    float *Lh, *Ch, *b1L, *b1C, *b2L, *b2C, *mlpL, *mlpC, *msgL, *msgC;
    float *gatesC, *gatesL, *partials;
    float *LC1h,*LC1l,*LC2h,*LC2l,*LC3h,*LC3l,*CL1h,*CL1l,*CL2h,*CL2l,*CL3h,*CL3l;
    float *CWih,*CWil,*CWhh,*CWhl,*LWih,*LWil,*LWhh,*LWhl,*VW1h,*VW1l,*VW2h,*VW2l;
    SYM(Lh, g_Lh); SYM(Ch, g_Ch);
    SYM(b1L, g_b1L); SYM(b1C, g_b1C); SYM(b2L, g_b2L); SYM(b2C, g_b2C);
    SYM(mlpL, g_mlpL); SYM(mlpC, g_mlpC); SYM(msgL, g_msgL); SYM(msgC, g_msgC);
    SYM(gatesC, g_gatesC); SYM(gatesL, g_gatesL); SYM(partials, g_partials);
    SYM(LC1h, g_LC1h); SYM(LC1l, g_LC1l); SYM(LC2h, g_LC2h); SYM(LC2l, g_LC2l);
    SYM(LC3h, g_LC3h); SYM(LC3l, g_LC3l);
    SYM(CL1h, g_CL1h); SYM(CL1l, g_CL1l); SYM(CL2h, g_CL2h); SYM(CL2l, g_CL2l);
    SYM(CL3h, g_CL3h); SYM(CL3l, g_CL3l);
    SYM(CWih, g_CWih); SYM(CWil, g_CWil); SYM(CWhh, g_CWhh); SYM(CWhl, g_CWhl);
    SYM(LWih, g_LWih); SYM(LWil, g_LWil); SYM(LWhh, g_LWhh); SYM(LWhl, g_LWhl);
    SYM(VW1h, g_VW1h); SYM(VW1l, g_VW1l); SYM(VW2h, g_VW2h); SYM(VW2l, g_VW2l);

    // ---- setup: 3 launches ----
    build_both_kernel<<<LIT_BLOCKS + CLS_BLOCKS, 256>>>(M);

    WSplitAll ws = {{
        {LC_W1, LC1h, LC1l, H1, E,  E},
        {LC_W2, LC2h, LC2l, H2, H1, K2P},
        {LC_W3, LC3h, LC3l, E,  H2, K3P},
        {CL_W1, CL1h, CL1l, H1, E,  E},
        {CL_W2, CL2h, CL2l, H2, H1, K2P},
        {CL_W3, CL3h, CL3l, E,  H2, K3P},
        {C_Wih, CWih, CWil, NG, E,  E},
        {C_Whh, CWhh, CWhl, NG, E,  E},
        {L_Wih, LWih, LWil, NG, E,  E},
        {L_Whh, LWhh, LWhl, NG, E,  E},
        {V_W1,  VW1h, VW1l, H1, E,  E},
        {V_W2,  VW2h, VW2l, H2, H1, K2P},
    }};
    dim3 sg((H2 * K2P + 255) / 256, 12);
    split_all_kernel<<<sg, 256>>>(ws);

    init_states_kernel<<<((NLITS + NCLS) * E + 255) / 256, 256>>>(L_init, C_init);

    GP dummy = {};

    for (int t = 0; t < TSTEPS; t++) {
        // MLP L1 (relu), out pitch K2P (pad cols stay 0)
        GP a1 = {{Lh}, {LC1h}, {LC1l}, LC_b1, b1L, NLITS, 1};
        GP b1 = {{Ch}, {CL1h}, {CL1l}, CL_b1, b1C, NCLS, 1};
        launch_gemm<true>(a1, b1, 2, H1, E, K2P);

        // MLP L2 (relu), K=416, out pitch K3P
        GP a2 = {{b1L}, {LC2h}, {LC2l}, LC_b2, b2L, NLITS, 1};
        GP b2 = {{b1C}, {CL2h}, {CL2l}, CL_b2, b2C, NCLS, 1};
        launch_gemm<true>(a2, b2, 2, H2, K2P, K3P);

        // MLP L3 (no relu), K=224
        GP a3 = {{b2L}, {LC3h}, {LC3l}, LC_b3, mlpL, NLITS, 1};
        GP b3 = {{b2C}, {CL3h}, {CL3l}, CL_b3, mlpC, NCLS, 1};
        launch_gemm<false>(a3, b3, 2, E, K3P, E);

        // sparse aggregation
        spmm_both_kernel<<<(NCLS + NLITS + 7) / 8, 256>>>();

        // LSTM gates: msgs@Wih^T + h@Whh^T + b (pre-update h)
        GP ga = {{msgC, Ch}, {CWih, CWhh}, {CWil, CWhl}, C_b, gatesC, NCLS, 2};
        GP gb = {{msgL, Lh}, {LWih, LWhh}, {LWil, LWhl}, L_b, gatesL, NLITS, 2};
        launch_gemm<false>(ga, gb, 2, NG, E, NG);

        // pointwise state update
        lstm_pointwise_both<<<((NCLS + NLITS) * E + 255) / 256, 256>>>();
    }

    // final vote MLP + mean + logit
    GP v1 = {{Lh}, {VW1h}, {VW1l}, V_b1, b1L, NLITS, 1};
    launch_gemm<true>(v1, dummy, 1, H1, E, K2P);
    GP v2 = {{b1L}, {VW2h}, {VW2l}, V_b2, b2L, NLITS, 1};
    launch_gemm<true>(v2, dummy, 1, H2, K2P, K3P);
    vote_partial_kernel<<<VOTE_BLOCKS, 256>>>(b2L, V_W3, V_b3, partials);
    finalize_kernel<<<1, 512>>>(partials, VOTE_BLOCKS, out);
}

// round 16
// speedup vs baseline: 1.2267x; 1.0160x over previous
#include <cuda_runtime.h>
#include <math.h>
#include <stdint.h>

// ---------------- problem constants ----------------
#define NLITS 4000
#define NCLS  8000
#define E     128
#define H1    400
#define H2    200
#define K2P   416          // H1 padded to multiple of 32
#define K3P   224          // H2 padded to multiple of 32
#define NG    512          // 4*E LSTM gates
#define TSTEPS 30
#define LIT_STRIDE 512
#define CLS_STRIDE 256
#define VOTE_BLOCKS ((NLITS + 7) / 8)

// GEMM tiling: block tile 128(M) x 64(N), 8 warps stacked over M (warp tile 16x64), BK=32
#define BK 32
#define SPBB 144                 // smem row stride bytes (32 floats + 4 pad)
#define TILEB_A (128 * SPBB)     // 18432 B
#define TILEB_B (64 * SPBB)      // 9216 B
#define STAGE_BYTES (TILEB_A + 2 * TILEB_B)   // A, Bh, Bl = 36864 B
#define STAGES 3
#define GEMM_SMEM (STAGES * STAGE_BYTES)      // 110592 B; 2 blocks/SM

// ---------------- device scratch (static, BSS zero-init, allocation-free) ----------------
__device__ float g_Lh[NLITS * E], g_Lc[NLITS * E];
__device__ float g_Ch[NCLS * E],  g_Cc[NCLS * E];
__device__ float g_b1L[NLITS * K2P], g_b1C[NCLS * K2P];   // pad cols [400,416) stay 0
__device__ float g_b2L[NLITS * K3P], g_b2C[NCLS * K3P];   // pad cols [200,224) stay 0
__device__ float g_mlpL[NLITS * E],  g_mlpC[NCLS * E];
__device__ float g_msgL[NLITS * E],  g_msgC[NCLS * E];
__device__ float g_gatesC[NCLS * NG], g_gatesL[NLITS * NG];

// pre-split weights (tf32-valued fp32 hi/lo), K padded to mult of 32
__device__ float g_LC1h[H1 * E],    g_LC1l[H1 * E];
__device__ float g_LC2h[H2 * K2P],  g_LC2l[H2 * K2P];
__device__ float g_LC3h[E * K3P],   g_LC3l[E * K3P];
__device__ float g_CL1h[H1 * E],    g_CL1l[H1 * E];
__device__ float g_CL2h[H2 * K2P],  g_CL2l[H2 * K2P];
__device__ float g_CL3h[E * K3P],   g_CL3l[E * K3P];
__device__ float g_CWih[NG * E],    g_CWil[NG * E];
__device__ float g_CWhh[NG * E],    g_CWhl[NG * E];
__device__ float g_LWih[NG * E],    g_LWil[NG * E];
__device__ float g_LWhh[NG * E],    g_LWhl[NG * E];
__device__ float g_VW1h[H1 * E],    g_VW1l[H1 * E];
__device__ float g_VW2h[H2 * K2P],  g_VW2l[H2 * K2P];

__device__ int   g_lit_idx[(size_t)NLITS * LIT_STRIDE];
__device__ int   g_lit_len[NLITS];
__device__ int   g_cls_idx[(size_t)NCLS * CLS_STRIDE];
__device__ int   g_cls_len[NCLS];
__device__ float g_partials[VOTE_BLOCKS];

// ---------------- helpers ----------------
__device__ __forceinline__ unsigned smem_u32(const void* p) {
    return (unsigned)__cvta_generic_to_shared(p);
}
__device__ __forceinline__ void tf32_split(float v, uint32_t& h, uint32_t& l) {
    asm("cvt.rna.tf32.f32 %0, %1;" : "=r"(h) : "f"(v));
    float r = v - __uint_as_float(h);
    asm("cvt.rna.tf32.f32 %0, %1;" : "=r"(l) : "f"(r));
}
__device__ __forceinline__ void cp16(uint32_t dst, const void* src, bool valid) {
    int sz = valid ? 16 : 0;
    asm volatile("cp.async.cg.shared.global [%0], [%1], 16, %2;"
                 :: "r"(dst), "l"(src), "r"(sz) : "memory");
}
#define CP_COMMIT() asm volatile("cp.async.commit_group;" ::: "memory")
#define CP_WAIT1()  asm volatile("cp.async.wait_group 1;" ::: "memory")
#define CP_WAIT0()  asm volatile("cp.async.wait_group 0;" ::: "memory")

#define LDSM4(R0, R1, R2, R3, ADDR)                                          \
    asm volatile("ldmatrix.sync.aligned.m8n8.x4.shared.b16 {%0,%1,%2,%3}, [%4];" \
                 : "=r"(R0), "=r"(R1), "=r"(R2), "=r"(R3) : "r"(ADDR))

#define MMA_TF32(C, A, B)                                              \
    asm volatile(                                                      \
        "mma.sync.aligned.m16n8k8.row.col.f32.tf32.tf32.f32 "          \
        "{%0,%1,%2,%3}, {%4,%5,%6,%7}, {%8,%9}, {%0,%1,%2,%3};"        \
        : "+f"((C)[0]), "+f"((C)[1]), "+f"((C)[2]), "+f"((C)[3])       \
        : "r"((A)[0]), "r"((A)[1]), "r"((A)[2]), "r"((A)[3]),          \
          "r"((B)[0]), "r"((B)[1]))

__device__ __forceinline__ float sigmoidf_(float x) { return 1.0f / (1.0f + expf(-x)); }

// ---------------- merged adjacency builder (1 launch) ----------------
#define LIT_BLOCKS ((NLITS + 7) / 8)
#define CLS_BLOCKS ((NCLS + 7) / 8)

__global__ void build_both_kernel(const float* __restrict__ M) {
    int lane = threadIdx.x & 31;
    int wslot = threadIdx.x >> 5;
    if (blockIdx.x < LIT_BLOCKS) {
        int l = blockIdx.x * 8 + wslot;
        if (l >= NLITS) return;
        const float* row = M + (size_t)l * NCLS;
        int cnt = 0;
        for (int c0 = 0; c0 < NCLS; c0 += 32) {
            float v = row[c0 + lane];
            unsigned mask = __ballot_sync(0xffffffffu, v != 0.0f);
            if (v != 0.0f) {
                int pos = cnt + __popc(mask & ((1u << lane) - 1u));
                if (pos < LIT_STRIDE) g_lit_idx[(size_t)l * LIT_STRIDE + pos] = c0 + lane;
            }
            cnt += __popc(mask);
        }
        if (lane == 0) g_lit_len[l] = cnt < LIT_STRIDE ? cnt : LIT_STRIDE;
    } else {
        int c = (blockIdx.x - LIT_BLOCKS) * 8 + wslot;
        if (c >= NCLS) return;
        int cnt = 0;
        for (int l0 = 0; l0 < NLITS; l0 += 32) {
            float v = M[(size_t)(l0 + lane) * NCLS + c];
            unsigned mask = __ballot_sync(0xffffffffu, v != 0.0f);
            if (v != 0.0f) {
                int pos = cnt + __popc(mask & ((1u << lane) - 1u));
                if (pos < CLS_STRIDE) g_cls_idx[(size_t)c * CLS_STRIDE + pos] = l0 + lane;
            }
            cnt += __popc(mask);
        }
        if (lane == 0) g_cls_len[c] = cnt < CLS_STRIDE ? cnt : CLS_STRIDE;
    }
}

// ---------------- consolidated weight splitter (1 launch, 12 weights) ----------------
struct WSplit { const float* in; float* hi; float* lo; int rows, K, KP; };
struct WSplitAll { WSplit w[12]; };

__global__ void split_all_kernel(WSplitAll all) {
    const WSplit w = all.w[blockIdx.y];
    int i = blockIdx.x * blockDim.x + threadIdx.x;
    if (i >= w.rows * w.KP) return;
    int r = i / w.KP, k = i - r * w.KP;
    float v = (k < w.K) ? w.in[(size_t)r * w.K + k] : 0.0f;
    uint32_t h, l;
    tf32_split(v, h, l);
    w.hi[i] = __uint_as_float(h);
    w.lo[i] = __uint_as_float(l);
}

// ---------------- state init ----------------
__global__ void init_states_kernel(const float* __restrict__ L_init,
                                   const float* __restrict__ C_init) {
    int i = blockIdx.x * blockDim.x + threadIdx.x;
    const int totL = NLITS * E;
    if (i < totL) {
        g_Lh[i] = L_init[i & (E - 1)]; g_Lc[i] = 0.0f;
    } else if (i < totL + NCLS * E) {
        int j = i - totL;
        g_Ch[j] = C_init[j & (E - 1)]; g_Cc[j] = 0.0f;
    }
}

// ---------------- tf32x3 mma GEMM, BK=32, warp tile 16(M) x 64(N) ----------------
struct GP {
    const float* A[2];
    const float* Bh[2];
    const float* Bl[2];
    const float* bias;
    float* out;
    int M;
    int nseg;
};

template <bool RELU>
__global__ void __launch_bounds__(256, 2) gemm_tf32x3_kernel(GP p0, GP p1, int N, int K, int opitch)
{
    const GP p = (blockIdx.z == 0) ? p0 : p1;
    const int m0 = blockIdx.y * 128;
    if (m0 >= p.M) return;
    const int n0 = blockIdx.x * 64;

    extern __shared__ char smem[];
    const uint32_t sb = smem_u32(smem);

    const int tid = threadIdx.x;
    const int lane = tid & 31;
    const int wid = tid >> 5;
    const int wm0 = wid * 16;         // 8 warps stacked over M
    const int grp = lane >> 2;
    const int q = lane & 3;
    const int sel = lane >> 3;

    const int ntiles = K >> 5;          // BK=32
    const int total = ntiles * p.nseg;

    float c[8][4];                      // 16x64 warp tile: 8 n8-tiles x 4
#pragma unroll
    for (int b = 0; b < 8; b++)
#pragma unroll
        for (int d = 0; d < 4; d++) c[b][d] = 0.0f;

    auto load_stage = [&](int ti, int stage) {
        const int seg = ti / ntiles;
        const int k0 = (ti - seg * ntiles) << 5;
        const float* Ap  = p.A[seg];
        const float* Bph = p.Bh[seg];
        const float* Bpl = p.Bl[seg];
        const uint32_t base = sb + stage * STAGE_BYTES;
#pragma unroll
        for (int i = 0; i < 4; i++) {
            int cid = tid + i * 256;
            int row = cid >> 3;
            int ch = cid & 7;
            bool va = (m0 + row < p.M);
            int ra = va ? (m0 + row) : 0;
            cp16(base + row * SPBB + ch * 16, Ap + (size_t)ra * K + k0 + ch * 4, va);
        }
#pragma unroll
        for (int i = 0; i < 2; i++) {
            int cid = tid + i * 256;
            int row = cid >> 3;
            int ch = cid & 7;
            bool vb = (n0 + row < N);
            int rb = vb ? (n0 + row) : 0;
            uint32_t doff = row * SPBB + ch * 16;
            size_t goff = (size_t)rb * K + k0 + ch * 4;
            cp16(base + TILEB_A + doff,           Bph + goff, vb);
            cp16(base + TILEB_A + TILEB_B + doff, Bpl + goff, vb);
        }
        CP_COMMIT();
    };

    load_stage(0, 0);
    if (total > 1) load_stage(1, 1);
    else CP_COMMIT();

    for (int t = 0; t < total; t++) {
        if (t + 1 < total) { CP_WAIT1(); } else { CP_WAIT0(); }
        __syncthreads();

        if (t + 2 < total) load_stage(t + 2, (t + 2) % STAGES);

        const int st = (t % STAGES) * STAGE_BYTES;
        const uint32_t Ab  = sb + st;
        const uint32_t Bhb = sb + st + TILEB_A;
        const uint32_t Blb = sb + st + TILEB_A + TILEB_B;

#pragma unroll
        for (int kk = 0; kk < 4; kk++) {
            const int cb = kk * 8;

            // single A fragment (16 rows x k8), split to hi/lo in regs
            uint32_t ah[4], al[4];
            {
                int rowa = wm0 + (lane & 7) + ((sel & 1) << 3);
                int cola = cb + ((sel >> 1) << 2);
                uint32_t r0, r1, r2, r3;
                LDSM4(r0, r1, r2, r3, Ab + rowa * SPBB + cola * 4);
                tf32_split(__uint_as_float(r0), ah[0], al[0]);
                tf32_split(__uint_as_float(r1), ah[1], al[1]);
                tf32_split(__uint_as_float(r2), ah[2], al[2]);
                tf32_split(__uint_as_float(r3), ah[3], al[3]);
            }

            // B fragments: 4 ldsm pairs cover all 64 N cols (8 n8-tiles)
            uint32_t bhf[4][4], blf[4][4];
#pragma unroll
            for (int ngp = 0; ngp < 4; ngp++) {
                int rowb = ngp * 16 + (lane & 7) + ((sel >> 1) << 3);
                int colb = cb + ((sel & 1) << 2);
                LDSM4(bhf[ngp][0], bhf[ngp][1], bhf[ngp][2], bhf[ngp][3],
                      Bhb + rowb * SPBB + colb * 4);
                LDSM4(blf[ngp][0], blf[ngp][1], blf[ngp][2], blf[ngp][3],
                      Blb + rowb * SPBB + colb * 4);
            }

            // term-major mma issue (per-accumulator order: hh, hl, lh)
#pragma unroll
            for (int ngp = 0; ngp < 4; ngp++) {
                MMA_TF32(c[2 * ngp],     ah, (&bhf[ngp][0]));
                MMA_TF32(c[2 * ngp + 1], ah, (&bhf[ngp][2]));
            }
#pragma unroll
            for (int ngp = 0; ngp < 4; ngp++) {
                MMA_TF32(c[2 * ngp],     ah, (&blf[ngp][0]));
                MMA_TF32(c[2 * ngp + 1], ah, (&blf[ngp][2]));
            }
#pragma unroll
            for (int ngp = 0; ngp < 4; ngp++) {
                MMA_TF32(c[2 * ngp],     al, (&bhf[ngp][0]));
                MMA_TF32(c[2 * ngp + 1], al, (&bhf[ngp][2]));
            }
        }
    }

    // epilogue: + bias, optional relu, guarded fp32 store
#pragma unroll
    for (int ng = 0; ng < 8; ng++) {
        int col = n0 + ng * 8 + q * 2;
        if (col >= N) continue;
        float b0 = p.bias[col], b1 = p.bias[col + 1];
#pragma unroll
        for (int half = 0; half < 2; half++) {
            int row = m0 + wm0 + grp + half * 8;
            if (row >= p.M) continue;
            float v0 = c[ng][half * 2 + 0] + b0;
            float v1 = c[ng][half * 2 + 1] + b1;
            if (RELU) { v0 = fmaxf(v0, 0.0f); v1 = fmaxf(v1, 0.0f); }
            *(float2*)(p.out + (size_t)row * opitch + col) = make_float2(v0, v1);
        }
    }
}

template <bool RELU>
static inline void launch_gemm(GP p0, GP p1, int nz, int N, int K, int opitch) {
    cudaFuncSetAttribute(gemm_tf32x3_kernel<RELU>,
                         cudaFuncAttributeMaxDynamicSharedMemorySize, GEMM_SMEM);
    int mmax = p0.M;
    if (nz > 1 && p1.M > mmax) mmax = p1.M;
    dim3 grid((N + 63) / 64, (mmax + 127) / 128, nz);
    gemm_tf32x3_kernel<RELU><<<grid, 256, GEMM_SMEM>>>(p0, p1, N, K, opitch);
}

// ---------------- combined SpMM gather (both directions) ----------------
__global__ void spmm_both_kernel() {
    int r = (blockIdx.x * blockDim.x + threadIdx.x) >> 5;
    if (r >= NCLS + NLITS) return;
    int lane = threadIdx.x & 31;

    const int* lst; int n; const float* in; float* outp;
    if (r < NCLS) {
        lst = g_cls_idx + (size_t)r * CLS_STRIDE; n = g_cls_len[r];
        in = g_mlpL; outp = g_msgC + (size_t)r * E;
    } else {
        int rr = r - NCLS;
        lst = g_lit_idx + (size_t)rr * LIT_STRIDE; n = g_lit_len[rr];
        in = g_mlpC; outp = g_msgL + (size_t)rr * E;
    }

    float4 acc = make_float4(0.f, 0.f, 0.f, 0.f);
    int j = 0;
    for (; j + 4 <= n; j += 4) {
        int i0 = lst[j], i1 = lst[j + 1], i2 = lst[j + 2], i3 = lst[j + 3];
        float4 v0 = ((const float4*)(in + (size_t)i0 * E))[lane];
        float4 v1 = ((const float4*)(in + (size_t)i1 * E))[lane];
        float4 v2 = ((const float4*)(in + (size_t)i2 * E))[lane];
        float4 v3 = ((const float4*)(in + (size_t)i3 * E))[lane];
        acc.x += v0.x + v1.x + v2.x + v3.x;
        acc.y += v0.y + v1.y + v2.y + v3.y;
        acc.z += v0.z + v1.z + v2.z + v3.z;
        acc.w += v0.w + v1.w + v2.w + v3.w;
    }
    for (; j < n; j++) {
        float4 v = ((const float4*)(in + (size_t)lst[j] * E))[lane];
        acc.x += v.x; acc.y += v.y; acc.z += v.z; acc.w += v.w;
    }
    ((float4*)outp)[lane] = acc;
}

// ---------------- LSTM pointwise (both node types) ----------------
__global__ void lstm_pointwise_both() {
    int i = blockIdx.x * blockDim.x + threadIdx.x;
    const int totalC = NCLS * E;
    if (i >= totalC + NLITS * E) return;

    const float* gmat; float* cvec; float* hvec; int e;
    if (i < totalC) { gmat = g_gatesC; cvec = g_Cc; hvec = g_Ch; e = i; }
    else            { gmat = g_gatesL; cvec = g_Lc; hvec = g_Lh; e = i - totalC; }

    int row = e >> 7;
    int col = e & (E - 1);
    const float* gr = gmat + (size_t)row * NG;
    float ig = sigmoidf_(gr[col]);
    float fg = sigmoidf_(gr[E + col]);
    float gg = tanhf(gr[2 * E + col]);
    float og = sigmoidf_(gr[3 * E + col]);
    float c2 = fg * cvec[e] + ig * gg;
    cvec[e] = c2;
    hvec[e] = og * tanhf(c2);
}

// ---------------- vote + reduction ----------------
__global__ void vote_partial_kernel(const float* __restrict__ X2,
                                    const float* __restrict__ W3,
                                    const float* __restrict__ b3,
                                    float* __restrict__ partials) {
    int warp = (blockIdx.x * blockDim.x + threadIdx.x) >> 5;
    int lane = threadIdx.x & 31;
    float vote = 0.0f;
    if (warp < NLITS) {
        const float* x = X2 + (size_t)warp * K3P;
        float s = 0.0f;
        for (int jj = lane; jj < H2; jj += 32) s += x[jj] * W3[jj];
#pragma unroll
        for (int o = 16; o; o >>= 1) s += __shfl_down_sync(0xffffffffu, s, o);
        if (lane == 0) vote = sigmoidf_(s + b3[0]);
    }
    __shared__ float sm[8];
    if (lane == 0) sm[threadIdx.x >> 5] = vote;
    __syncthreads();
    if (threadIdx.x == 0) {
        float t = 0.0f;
        for (int w = 0; w < 8; w++) t += sm[w];
        partials[blockIdx.x] = t;
    }
}

__global__ void finalize_kernel(const float* __restrict__ partials, int n,
                                float* __restrict__ out) {
    __shared__ float sm[512];
    float s = 0.0f;
    for (int i = threadIdx.x; i < n; i += blockDim.x) s += partials[i];
    sm[threadIdx.x] = s;
    __syncthreads();
    for (int o = 256; o; o >>= 1) {
        if (threadIdx.x < o) sm[threadIdx.x] += sm[threadIdx.x + o];
        __syncthreads();
    }
    if (threadIdx.x == 0) {
        float avg = sm[0] / (float)NLITS;
        out[0] = logf(avg / (1.0f - avg));
    }
}

// ---------------- host ----------------
#define SYM(var, sym) cudaGetSymbolAddress((void**)&var, sym)

extern "C" void kernel_launch(void* const* d_in, const int* in_sizes, int n_in,
                              void* d_out, int out_size) {
    const float* M      = (const float*)d_in[0];
    const float* L_init = (const float*)d_in[1];
    const float* C_init = (const float*)d_in[2];
    const float* LC_W1 = (const float*)d_in[3];  const float* LC_b1 = (const float*)d_in[4];
    const float* LC_W2 = (const float*)d_in[5];  const float* LC_b2 = (const float*)d_in[6];
    const float* LC_W3 = (const float*)d_in[7];  const float* LC_b3 = (const float*)d_in[8];
    const float* CL_W1 = (const float*)d_in[9];  const float* CL_b1 = (const float*)d_in[10];
    const float* CL_W2 = (const float*)d_in[11]; const float* CL_b2 = (const float*)d_in[12];
    const float* CL_W3 = (const float*)d_in[13]; const float* CL_b3 = (const float*)d_in[14];
    const float* L_Wih = (const float*)d_in[15]; const float* L_Whh = (const float*)d_in[16];
    const float* L_b   = (const float*)d_in[17];
    const float* C_Wih = (const float*)d_in[18]; const float* C_Whh = (const float*)d_in[19];
    const float* C_b   = (const float*)d_in[20];
    const float* V_W1 = (const float*)d_in[21];  const float* V_b1 = (const float*)d_in[22];
    const float* V_W2 = (const float*)d_in[23];  const float* V_b2 = (const float*)d_in[24];
    const float* V_W3 = (const float*)d_in[25];  const float* V_b3 = (const float*)d_in[26];
    float* out = (float*)d_out;

    float *Lh, *Ch, *b1L, *b1C, *b2L, *b2C, *mlpL, *mlpC, *msgL, *msgC;
    float *gatesC, *gatesL, *partials;
    float *LC1h,*LC1l,*LC2h,*LC2l,*LC3h,*LC3l,*CL1h,*CL1l,*CL2h,*CL2l,*CL3h,*CL3l;
    float *CWih,*CWil,*CWhh,*CWhl,*LWih,*LWil,*LWhh,*LWhl,*VW1h,*VW1l,*VW2h,*VW2l;
    SYM(Lh, g_Lh); SYM(Ch, g_Ch);
    SYM(b1L, g_b1L); SYM(b1C, g_b1C); SYM(b2L, g_b2L); SYM(b2C, g_b2C);
    SYM(mlpL, g_mlpL); SYM(mlpC, g_mlpC); SYM(msgL, g_msgL); SYM(msgC, g_msgC);
    SYM(gatesC, g_gatesC); SYM(gatesL, g_gatesL); SYM(partials, g_partials);
    SYM(LC1h, g_LC1h); SYM(LC1l, g_LC1l); SYM(LC2h, g_LC2h); SYM(LC2l, g_LC2l);
    SYM(LC3h, g_LC3h); SYM(LC3l, g_LC3l);
    SYM(CL1h, g_CL1h); SYM(CL1l, g_CL1l); SYM(CL2h, g_CL2h); SYM(CL2l, g_CL2l);
    SYM(CL3h, g_CL3h); SYM(CL3l, g_CL3l);
    SYM(CWih, g_CWih); SYM(CWil, g_CWil); SYM(CWhh, g_CWhh); SYM(CWhl, g_CWhl);
    SYM(LWih, g_LWih); SYM(LWil, g_LWil); SYM(LWhh, g_LWhh); SYM(LWhl, g_LWhl);
    SYM(VW1h, g_VW1h); SYM(VW1l, g_VW1l); SYM(VW2h, g_VW2h); SYM(VW2l, g_VW2l);

    // ---- setup: 3 launches ----
    build_both_kernel<<<LIT_BLOCKS + CLS_BLOCKS, 256>>>(M);

    WSplitAll ws = {{
        {LC_W1, LC1h, LC1l, H1, E,  E},
        {LC_W2, LC2h, LC2l, H2, H1, K2P},
        {LC_W3, LC3h, LC3l, E,  H2, K3P},
        {CL_W1, CL1h, CL1l, H1, E,  E},
        {CL_W2, CL2h, CL2l, H2, H1, K2P},
        {CL_W3, CL3h, CL3l, E,  H2, K3P},
        {C_Wih, CWih, CWil, NG, E,  E},
        {C_Whh, CWhh, CWhl, NG, E,  E},
        {L_Wih, LWih, LWil, NG, E,  E},
        {L_Whh, LWhh, LWhl, NG, E,  E},
        {V_W1,  VW1h, VW1l, H1, E,  E},
        {V_W2,  VW2h, VW2l, H2, H1, K2P},
    }};
    dim3 sg((H2 * K2P + 255) / 256, 12);
    split_all_kernel<<<sg, 256>>>(ws);

    init_states_kernel<<<((NLITS + NCLS) * E + 255) / 256, 256>>>(L_init, C_init);

    GP dummy = {};

    for (int t = 0; t < TSTEPS; t++) {
        // MLP L1 (relu), out pitch K2P (pad cols stay 0)
        GP a1 = {{Lh}, {LC1h}, {LC1l}, LC_b1, b1L, NLITS, 1};
        GP b1 = {{Ch}, {CL1h}, {CL1l}, CL_b1, b1C, NCLS, 1};
        launch_gemm<true>(a1, b1, 2, H1, E, K2P);

        // MLP L2 (relu), K=416, out pitch K3P
        GP a2 = {{b1L}, {LC2h}, {LC2l}, LC_b2, b2L, NLITS, 1};
        GP b2 = {{b1C}, {CL2h}, {CL2l}, CL_b2, b2C, NCLS, 1};
        launch_gemm<true>(a2, b2, 2, H2, K2P, K3P);

        // MLP L3 (no relu), K=224
        GP a3 = {{b2L}, {LC3h}, {LC3l}, LC_b3, mlpL, NLITS, 1};
        GP b3 = {{b2C}, {CL3h}, {CL3l}, CL_b3, mlpC, NCLS, 1};
        launch_gemm<false>(a3, b3, 2, E, K3P, E);

        // sparse aggregation
        spmm_both_kernel<<<(NCLS + NLITS + 7) / 8, 256>>>();

        // LSTM gates: msgs@Wih^T + h@Whh^T + b (pre-update h)
        GP ga = {{msgC, Ch}, {CWih, CWhh}, {CWil, CWhl}, C_b, gatesC, NCLS, 2};
        GP gb = {{msgL, Lh}, {LWih, LWhh}, {LWil, LWhl}, L_b, gatesL, NLITS, 2};
        launch_gemm<false>(ga, gb, 2, NG, E, NG);

        // pointwise state update
        lstm_pointwise_both<<<((NCLS + NLITS) * E + 255) / 256, 256>>>();
    }

    // final vote MLP + mean + logit
    GP v1 = {{Lh}, {VW1h}, {VW1l}, V_b1, b1L, NLITS, 1};
    launch_gemm<true>(v1, dummy, 1, H1, E, K2P);
    GP v2 = {{b1L}, {VW2h}, {VW2l}, V_b2, b2L, NLITS, 1};
    launch_gemm<true>(v2, dummy, 1, H2, K2P, K3P);
    vote_partial_kernel<<<VOTE_BLOCKS, 256>>>(b2L, V_W3, V_b3, partials);
    finalize_kernel<<<1, 512>>>(partials, VOTE_BLOCKS, out);
}